// round 15
// baseline (speedup 1.0000x reference)
#include <cuda_runtime.h>
#include <cuda_fp16.h>
#include <cstdint>

#define Bn 32
#define Cn 256
#define Tn 4096

// Static device scratch (allocation-guard legal).
__device__ float4   g_e4[(size_t)Bn * Cn * Cn / 4];      //  8 MB P = S + M (fp32)
__device__ float4   g_m4[(size_t)Bn * Cn * Cn / 4];      //  8 MB M = Xl*Xh^T (fp32)
__device__ uint32_t g_ah32[(size_t)Bn * Cn * Cn / 2];    //  4 MB attn hi (f16)
__device__ uint32_t g_xh32[(size_t)Bn * Cn * Tn / 2];    // 67 MB X hi  row-major
__device__ uint32_t g_xl32[(size_t)Bn * Cn * Tn / 2];    // 67 MB X lo  row-major
__device__ uint32_t g_xth32[(size_t)Bn * Tn * Cn / 2];   // 67 MB X^T hi

// ---------------------------------------------------------------------------
// Tile layout (proven): row = 64 k f16 = 128 B = 32 words; 16B group g at
// word offset row*32 + (g^(row&7))*4. cp.async / LDSM conflict-free.
// ---------------------------------------------------------------------------
__device__ __forceinline__ int woff(int row, int g) {
    return row * 32 + ((g ^ (row & 7)) << 2);
}
__device__ __forceinline__ uint32_t smem_u32(const void* p) {
    uint32_t a;
    asm("{ .reg .u64 t; cvta.to.shared.u64 t, %1; cvt.u32.u64 %0, t; }"
        : "=r"(a) : "l"(p));
    return a;
}
__device__ __forceinline__ uint32_t packh2(__half a, __half b) {
    return (uint32_t)__half_as_ushort(a) | ((uint32_t)__half_as_ushort(b) << 16);
}
__device__ __forceinline__ void mma_f16(float* d, const uint32_t* a, const uint32_t* b) {
    asm volatile(
        "mma.sync.aligned.m16n8k16.row.col.f32.f16.f16.f32 "
        "{%0,%1,%2,%3}, {%4,%5,%6,%7}, {%8,%9}, {%0,%1,%2,%3};"
        : "+f"(d[0]), "+f"(d[1]), "+f"(d[2]), "+f"(d[3])
        : "r"(a[0]), "r"(a[1]), "r"(a[2]), "r"(a[3]), "r"(b[0]), "r"(b[1]));
}
__device__ __forceinline__ void ldsm4(uint32_t& r0, uint32_t& r1, uint32_t& r2,
                                      uint32_t& r3, uint32_t addr) {
    asm volatile("ldmatrix.sync.aligned.m8n8.x4.shared.b16 {%0,%1,%2,%3}, [%4];"
                 : "=r"(r0), "=r"(r1), "=r"(r2), "=r"(r3) : "r"(addr));
}
__device__ __forceinline__ void lda_frag(uint32_t* a, uint32_t tb, int mrow,
                                         int ks, int lane) {
    int oct = lane >> 3, l7 = lane & 7;
    int row = mrow + ((oct & 1) << 3) + l7;
    int g = 2 * ks + (oct >> 1);
    ldsm4(a[0], a[1], a[2], a[3], tb + 4 * woff(row, g));
}
__device__ __forceinline__ void ldb_frag(uint32_t* b, uint32_t tb, int nrow,
                                         int ks, int lane) {
    int oct = lane >> 3, l7 = lane & 7;
    int row = nrow + ((oct >> 1) << 3) + l7;
    int g = 2 * ks + (oct & 1);
    ldsm4(b[0], b[1], b[2], b[3], tb + 4 * woff(row, g));
}
__device__ __forceinline__ void cp16(uint32_t saddr, const void* g) {
    asm volatile("cp.async.cg.shared.global [%0], [%1], 16;" :: "r"(saddr), "l"(g));
}
#define CP_COMMIT() asm volatile("cp.async.commit_group;" ::: "memory")
#define CP_WAIT(N)  asm volatile("cp.async.wait_group %0;" :: "n"(N) : "memory")

// ---------------------------------------------------------------------------
// Prepass v2 (wide ops): one read of X -> Xh (rm), Xl (rm), Xth, all f16.
// Tile 32c x 64t, 256 thr. Per thread: 2 LDG.128, 3 STG.128 + smem transpose.
// ---------------------------------------------------------------------------
__global__ __launch_bounds__(256) void split_pre(const float* __restrict__ x) {
    __shared__ __half ts[64][33];
    const int b = blockIdx.z, c0 = blockIdx.y * 32, t0 = blockIdx.x * 64;
    const int tid = threadIdx.x;
    const int cl = tid >> 3, tg = tid & 7;          // c-row 0..31, t-octet 0..7
    const int c = c0 + cl;

    const float* src = x + ((size_t)b * Cn + c) * Tn + t0 + tg * 8;
    float4 v0 = *(const float4*)src;
    float4 v1 = *(const float4*)(src + 4);

    float f[8] = {v0.x, v0.y, v0.z, v0.w, v1.x, v1.y, v1.z, v1.w};
    __half h[8];
    uint32_t H[4], L[4];
#pragma unroll
    for (int i = 0; i < 4; i++) {
        h[2 * i] = __float2half_rn(f[2 * i]);
        h[2 * i + 1] = __float2half_rn(f[2 * i + 1]);
        H[i] = packh2(h[2 * i], h[2 * i + 1]);
        L[i] = packh2(__float2half_rn(f[2 * i] - __half2float(h[2 * i])),
                      __float2half_rn(f[2 * i + 1] - __half2float(h[2 * i + 1])));
    }
    size_t wo = ((size_t)b * Cn + c) * (Tn / 2) + t0 / 2 + tg * 4;
    *(uint4*)(g_xh32 + wo) = make_uint4(H[0], H[1], H[2], H[3]);
    *(uint4*)(g_xl32 + wo) = make_uint4(L[0], L[1], L[2], L[3]);

#pragma unroll
    for (int k = 0; k < 8; k++) ts[tg * 8 + k][cl] = h[k];
    __syncthreads();

    // Xt: 64 t-rows x 16 words; thread -> (row = tid>>2, q = tid&3), 1 uint4.
    const int row = tid >> 2, q = tid & 3;
    uint32_t w[4];
#pragma unroll
    for (int wi = 0; wi < 4; wi++)
        w[wi] = packh2(ts[row][q * 8 + 2 * wi], ts[row][q * 8 + 2 * wi + 1]);
    size_t xo = ((size_t)b * Tn + t0 + row) * (Cn / 2) + c0 / 2 + q * 4;
    *(uint4*)(g_xth32 + xo) = make_uint4(w[0], w[1], w[2], w[3]);
}

// ---------------------------------------------------------------------------
// GEMM1 (symmetry trick): per tile compute S = Ah*Bh^T and M = Al*Bh^T only.
// E(i,j) = S(i,j) + M(i,j) + M(j,i) is assembled by softmax.
// CTA 128x128, 16 warps (32x32 tiles), BK=64, 3-stage cp.async.
// ---------------------------------------------------------------------------
__device__ __forceinline__ void g1_chunk(uint32_t sbase, float accS[8][4],
                                         float accM[8][4], int warpM, int warpN,
                                         int lane) {
    const uint32_t AH = sbase, AL = sbase + 4096 * 4, BH = sbase + 8192 * 4;
#pragma unroll
    for (int ks = 0; ks < 4; ks++) {
        uint32_t ah[2][4], al[2][4], bh[4][2];
#pragma unroll
        for (int ma = 0; ma < 2; ma++) lda_frag(ah[ma], AH, warpM + ma * 16, ks, lane);
#pragma unroll
        for (int ma = 0; ma < 2; ma++) lda_frag(al[ma], AL, warpM + ma * 16, ks, lane);
        ldb_frag(&bh[0][0], BH, warpN, ks, lane);
        ldb_frag(&bh[2][0], BH, warpN + 16, ks, lane);
#pragma unroll
        for (int ma = 0; ma < 2; ma++)
#pragma unroll
            for (int na = 0; na < 4; na++) {
                mma_f16(accS[ma * 4 + na], ah[ma], bh[na]);
                mma_f16(accM[ma * 4 + na], al[ma], bh[na]);
            }
    }
}

__global__ __launch_bounds__(512, 1) void gemm1_h() {
    extern __shared__ uint32_t sm[];
    const uint32_t sb = smem_u32(sm);
    const int tid = threadIdx.x, lane = tid & 31, wid = tid >> 5;
    const int gid = lane >> 2, tig = lane & 3;
    const int warpM = (wid >> 2) * 32, warpN = (wid & 3) * 32;
    const size_t pa = ((size_t)blockIdx.z * Cn + blockIdx.y * 128) * (Tn / 2);
    const size_t pb = ((size_t)blockIdx.z * Cn + blockIdx.x * 128) * (Tn / 2);
    const uint32_t* Ahp = g_xh32 + pa;
    const uint32_t* Alp = g_xl32 + pa;
    const uint32_t* Bhp = g_xh32 + pb;

    float accS[8][4], accM[8][4];
#pragma unroll
    for (int a = 0; a < 8; a++)
#pragma unroll
        for (int c = 0; c < 4; c++) { accS[a][c] = 0.f; accM[a][c] = 0.f; }

    auto issue = [&](int c, int s) {
        uint32_t st = sb + s * 12288 * 4;
#pragma unroll
        for (int it = 0; it < 2; it++) {
            int idx = it * 512 + tid, row = idx >> 3, g = idx & 7;
            int w4 = 4 * woff(row, g);
            size_t go = (size_t)row * (Tn / 2) + c * 32 + g * 4;
            cp16(st + w4, Ahp + go);
            cp16(st + 4096 * 4 + w4, Alp + go);
            cp16(st + 8192 * 4 + w4, Bhp + go);
        }
    };

    issue(0, 0); CP_COMMIT();
    issue(1, 1); CP_COMMIT();
    issue(2, 2); CP_COMMIT();
    CP_WAIT(2);
    __syncthreads();

    const int NC = Tn / 64;   // 64
#pragma unroll 1
    for (int c = 0; c < NC; c++) {
        g1_chunk(sb + (c % 3) * 12288 * 4, accS, accM, warpM, warpN, lane);
        if (c + 1 < NC) {
            __syncthreads();
            if (c + 3 < NC) issue(c + 3, c % 3);
            CP_COMMIT();
            CP_WAIT(2);
            __syncthreads();
        }
    }

    float* P = (float*)g_e4 + (size_t)blockIdx.z * Cn * Cn;
    float* Mm = (float*)g_m4 + (size_t)blockIdx.z * Cn * Cn;
#pragma unroll
    for (int ma = 0; ma < 2; ma++)
#pragma unroll
        for (int na = 0; na < 4; na++) {
            const float* s = accS[ma * 4 + na];
            const float* m = accM[ma * 4 + na];
            int r0 = blockIdx.y * 128 + warpM + ma * 16 + gid;
            int cc = blockIdx.x * 128 + warpN + na * 8 + 2 * tig;
            size_t o0 = (size_t)r0 * Cn + cc, o1 = (size_t)(r0 + 8) * Cn + cc;
            *(float2*)(P + o0) = make_float2(s[0] + m[0], s[1] + m[1]);
            *(float2*)(P + o1) = make_float2(s[2] + m[2], s[3] + m[3]);
            *(float2*)(Mm + o0) = make_float2(m[0], m[1]);
            *(float2*)(Mm + o1) = make_float2(m[2], m[3]);
        }
}

// ---------------------------------------------------------------------------
// Softmax: E(i,j) = P(i,j) + M(j,i); w = exp(min_e - e)/sum; writes f16 hi.
// ---------------------------------------------------------------------------
__global__ __launch_bounds__(256) void softmax_kernel() {
    const int row = blockIdx.x;               // b*Cn + i
    const int tid = threadIdx.x;
    const int i = row & (Cn - 1);
    const float* P = (float*)g_e4;
    const float* Mm = (float*)g_m4;

    float e = P[(size_t)row * Cn + tid] +
              Mm[((size_t)(row - i) + tid) * Cn + i];   // M(j=tid, i), batch base
    float v = e;
#pragma unroll
    for (int o = 16; o; o >>= 1) v = fminf(v, __shfl_xor_sync(0xffffffffu, v, o));
    __shared__ float red[8];
    __shared__ float bc[2];
    if ((tid & 31) == 0) red[tid >> 5] = v;
    __syncthreads();
    if (tid == 0) {
        float m = red[0];
#pragma unroll
        for (int k = 1; k < 8; k++) m = fminf(m, red[k]);
        bc[0] = m;
    }
    __syncthreads();
    float p = expf(bc[0] - e);
    v = p;
#pragma unroll
    for (int o = 16; o; o >>= 1) v += __shfl_xor_sync(0xffffffffu, v, o);
    if ((tid & 31) == 0) red[tid >> 5] = v;
    __syncthreads();
    if (tid == 0) {
        float s = 0.f;
#pragma unroll
        for (int k = 0; k < 8; k++) s += red[k];
        bc[1] = 1.0f / s;
    }
    __syncthreads();
    ((__half*)g_ah32)[(size_t)row * Cn + tid] = __float2half_rn(p * bc[1]);
}

// ---------------------------------------------------------------------------
// GEMM2 (single-product A): out = gamma*(Attn_h*X_h) + Xh. CTA 128x128,
// 8 warps (32x64 tiles), BK=64, 3-stage cp.async, 2 CTAs/SM.
// Residual read from f16 Xh (halves epilogue read traffic); streaming stores.
// ---------------------------------------------------------------------------
__device__ __forceinline__ void g2_chunk(uint32_t sbase, float acc[16][4],
                                         int warpM, int warpN, int lane) {
    const uint32_t AH = sbase, BH = sbase + 4096 * 4;
#pragma unroll
    for (int ks = 0; ks < 4; ks++) {
        uint32_t ah[2][4], bh[8][2];
#pragma unroll
        for (int ma = 0; ma < 2; ma++) lda_frag(ah[ma], AH, warpM + ma * 16, ks, lane);
#pragma unroll
        for (int p = 0; p < 4; p++) ldb_frag(&bh[2 * p][0], BH, warpN + p * 16, ks, lane);
#pragma unroll
        for (int ma = 0; ma < 2; ma++)
#pragma unroll
            for (int na = 0; na < 8; na++)
                mma_f16(acc[ma * 8 + na], ah[ma], bh[na]);
    }
}

__global__ __launch_bounds__(256, 2) void gemm2_h(const float* __restrict__ gamma,
                                                  float* __restrict__ out) {
    extern __shared__ uint32_t sm[];
    const uint32_t sb = smem_u32(sm);
    const int tid = threadIdx.x, lane = tid & 31, wid = tid >> 5;
    const int gid = lane >> 2, tig = lane & 3;
    const int warpM = (wid >> 1) * 32, warpN = (wid & 1) * 64;
    const int bz = blockIdx.z, by = blockIdx.y, t0 = blockIdx.x * 128;

    const uint32_t* Ah = g_ah32 + ((size_t)bz * Cn + by * 128) * 128;
    const uint32_t* Bh = g_xth32 + ((size_t)bz * Tn + t0) * 128;

    float acc[16][4];
#pragma unroll
    for (int a = 0; a < 16; a++)
#pragma unroll
        for (int c = 0; c < 4; c++) acc[a][c] = 0.f;

    auto issue = [&](int c, int s) {
        uint32_t st = sb + s * 8192 * 4;
#pragma unroll
        for (int it = 0; it < 4; it++) {
            int idx = it * 256 + tid, row = idx >> 3, g = idx & 7;
            int w4 = 4 * woff(row, g);
            cp16(st + w4, Ah + (size_t)row * 128 + c * 32 + g * 4);
            cp16(st + 4096 * 4 + w4, Bh + (size_t)row * 128 + c * 32 + g * 4);
        }
    };

    issue(0, 0); CP_COMMIT();
    issue(1, 1); CP_COMMIT();
    issue(2, 2); CP_COMMIT();
    CP_WAIT(2);
    __syncthreads();

    const int NC = Cn / 64;   // 4
#pragma unroll 1
    for (int c = 0; c < NC; c++) {
        g2_chunk(sb + (c % 3) * 8192 * 4, acc, warpM, warpN, lane);
        if (c + 1 < NC) {
            __syncthreads();
            if (c + 3 < NC) issue(c + 3, c % 3);
            CP_COMMIT();
            CP_WAIT(2);
            __syncthreads();
        }
    }

    const float gm = __ldg(gamma);
    const uint32_t* Xhb = g_xh32 + (size_t)bz * Cn * (Tn / 2);
    float* Ob = out + (size_t)bz * Cn * Tn;
#pragma unroll
    for (int ma = 0; ma < 2; ma++)
#pragma unroll
        for (int na = 0; na < 8; na++) {
            const float* d = acc[ma * 8 + na];
            int r0 = by * 128 + warpM + ma * 16 + gid;
            int cc = t0 + warpN + na * 8 + 2 * tig;
            uint32_t u0 = Xhb[(size_t)r0 * (Tn / 2) + (cc >> 1)];
            uint32_t u1 = Xhb[(size_t)(r0 + 8) * (Tn / 2) + (cc >> 1)];
            float2 x0 = __half22float2(*reinterpret_cast<__half2*>(&u0));
            float2 x1 = __half22float2(*reinterpret_cast<__half2*>(&u1));
            __stcs((float2*)(Ob + (size_t)r0 * Tn + cc),
                   make_float2(gm * d[0] + x0.x, gm * d[1] + x0.y));
            __stcs((float2*)(Ob + (size_t)(r0 + 8) * Tn + cc),
                   make_float2(gm * d[2] + x1.x, gm * d[3] + x1.y));
        }
}

// ---------------------------------------------------------------------------
extern "C" void kernel_launch(void* const* d_in, const int* in_sizes, int n_in,
                              void* d_out, int out_size) {
    (void)in_sizes; (void)n_in; (void)out_size;
    const float* x = (const float*)d_in[0];
    const float* gamma = (const float*)d_in[1];
    float* out = (float*)d_out;

    const int smem1 = 3 * 12288 * 4;   // 144 KB
    const int smem2 = 3 * 8192 * 4;    //  96 KB (x2 CTAs/SM = 192 KB)
    cudaFuncSetAttribute(gemm1_h, cudaFuncAttributeMaxDynamicSharedMemorySize, smem1);
    cudaFuncSetAttribute(gemm2_h, cudaFuncAttributeMaxDynamicSharedMemorySize, smem2);

    split_pre<<<dim3(Tn / 64, Cn / 32, Bn), 256>>>(x);
    gemm1_h<<<dim3(Cn / 128, Cn / 128, Bn), 512, smem1>>>();
    softmax_kernel<<<Bn * Cn, 256>>>();
    gemm2_h<<<dim3(Tn / 128, Cn / 128, Bn), 256, smem2>>>(gamma, out);
}